// round 10
// baseline (speedup 1.0000x reference)
#include <cuda_runtime.h>

// N-step discounted return, T=1024, B=4096, horizon=16, gamma=0.99.
// g[t,b] = sum_{h=0..15, t+h<T} g^h * r[t+h,b]*m[t+h,b]
//        + g^{min(t+16,T)-t} * V[min(t+15,T-1), b]
//
// Many-small-CTA design: block = 128 threads, tile = 32 cols x 64 rows,
// 2048 CTAs (~14/SM) so phase-1 loads of some CTAs overlap phase-2 compute
// of others — cross-CTA latency hiding instead of big-tile register pressure.
//  - entry:   prefetch 4 bootstrap-value float4 rows into registers
//  - phase 1: cooperative float4 loads, rm = rew*mask -> 10.25KB smem (80 rows)
//  - phase 2: thread = (col4 0..7, 4-row chunk 0..15); float4 backward sliding
//             recurrence S(t) = rm[t] + g*S(t+1) - g^16*rm[t+16].

#define TT 1024
#define BB 4096
#define HORIZON 16
#define BCOL 32                     // columns per block
#define TROWS 64                    // output rows per block
#define WROWS 80                    // staged rows (need 79; 80 = even split)
#define NTHR 128

constexpr float GAMMA = 0.99f;

__host__ __device__ constexpr float gpow(int n) {
    float x = 1.0f;
    for (int i = 0; i < n; ++i) x *= GAMMA;
    return x;
}

__device__ __constant__ float GP[17] = {
    gpow(0),  gpow(1),  gpow(2),  gpow(3),  gpow(4),  gpow(5),
    gpow(6),  gpow(7),  gpow(8),  gpow(9),  gpow(10), gpow(11),
    gpow(12), gpow(13), gpow(14), gpow(15), gpow(16)
};

__device__ __forceinline__ float4 f4_fma_s(float4 a, float s, float4 b) {
    return make_float4(fmaf(a.x, s, b.x), fmaf(a.y, s, b.y),
                       fmaf(a.z, s, b.z), fmaf(a.w, s, b.w));
}

__global__ __launch_bounds__(NTHR)
void nstep_return_kernel(const float* __restrict__ rew,
                         const float* __restrict__ val,
                         const float* __restrict__ msk,
                         float* __restrict__ out)
{
    __shared__ float rm[WROWS][BCOL];   // 80*32*4 = 10240 B

    const int tid   = threadIdx.x;
    const int bcol0 = blockIdx.x * BCOL;    // first column of this block
    const int t0    = blockIdx.y * TROWS;   // first output row of this block

    constexpr float G16 = gpow(16);

    // Phase-2 thread mapping (needed up front for the val prefetch).
    const int col4  = tid & 7;              // 0..7  -> cols [col4*4 .. col4*4+3]
    const int chunk = tid >> 3;             // 0..15 -> 4 rows each
    const int tl0   = chunk * 4;            // local row base
    const int c     = bcol0 + col4 * 4;     // global column of .x
    const int trow  = t0 + tl0;             // thread's first output row

    // ---- Entry: prefetch bootstrap values (in flight across phase 1 + bar) ----
    float4 vpre[4];
#pragma unroll
    for (int j = 0; j < 4; ++j) {
        const int vr = min(trow + j + HORIZON - 1, TT - 1);
        vpre[j] = *reinterpret_cast<const float4*>(val + (unsigned)(vr * BB + c));
    }

    // ---- Phase 1: stage rm = rew*mask for rows [t0, t0+WROWS) ----
    // 80 rows x 8 float4 = 640 slots = exactly 5 iterations of 128 threads.
#pragma unroll
    for (int it = 0; it < (WROWS * (BCOL / 4)) / NTHR; ++it) {
        const int i  = it * NTHR + tid;
        const int r  = i >> 3;              // row in tile
        const int c4 = i & 7;               // float4 index in row
        const int tt = t0 + r;

        float4 p = make_float4(0.f, 0.f, 0.f, 0.f);
        if (tt < TT) {
            const unsigned off = (unsigned)(tt * BB + bcol0 + c4 * 4);
            const float4 rv = *reinterpret_cast<const float4*>(rew + off);
            const float4 mv = *reinterpret_cast<const float4*>(msk + off);
            p = make_float4(rv.x * mv.x, rv.y * mv.y, rv.z * mv.z, rv.w * mv.w);
        }
        *reinterpret_cast<float4*>(&rm[r][c4 * 4]) = p;
    }
    __syncthreads();

    // ---- Phase 2: float4 sliding-window recurrence (smem + regs only) ----
    // S at local row tl0+3: Horner over rm rows [tl0+3 .. tl0+18].
    float4 S = make_float4(0.f, 0.f, 0.f, 0.f);
#pragma unroll
    for (int i = 18; i >= 3; --i) {
        const float4 x = *reinterpret_cast<const float4*>(&rm[tl0 + i][col4 * 4]);
        S = f4_fma_s(S, GAMMA, x);
    }

#pragma unroll
    for (int j = 3; j >= 0; --j) {
        const int t = trow + j;

        const float gb = (t + HORIZON <= TT) ? G16 : GP[TT - t];
        const float4 v = vpre[j];
        float4 o = make_float4(fmaf(gb, v.x, S.x), fmaf(gb, v.y, S.y),
                               fmaf(gb, v.z, S.z), fmaf(gb, v.w, S.w));
        *reinterpret_cast<float4*>(out + (unsigned)(t * BB + c)) = o;

        if (j > 0) {
            const float4 lo = *reinterpret_cast<const float4*>(&rm[tl0 + j - 1][col4 * 4]);
            const float4 hi = *reinterpret_cast<const float4*>(&rm[tl0 + j + 15][col4 * 4]);
            S = f4_fma_s(S, GAMMA, lo);                      // g*S + rm[t-1]
            S = make_float4(fmaf(-G16, hi.x, S.x), fmaf(-G16, hi.y, S.y),
                            fmaf(-G16, hi.z, S.z), fmaf(-G16, hi.w, S.w));
        }
    }
}

extern "C" void kernel_launch(void* const* d_in, const int* in_sizes, int n_in,
                              void* d_out, int out_size)
{
    const float* rewards = (const float*)d_in[0];
    const float* values  = (const float*)d_in[1];
    const float* masks   = (const float*)d_in[2];
    float*       out     = (float*)d_out;

    dim3 block(NTHR);
    dim3 grid(BB / BCOL, TT / TROWS);   // (128, 16) = 2048 blocks
    nstep_return_kernel<<<grid, block>>>(rewards, values, masks, out);
}

// round 11
// speedup vs baseline: 1.0573x; 1.0573x over previous
#include <cuda_runtime.h>
#include <cstdint>

// N-step discounted return, T=1024, B=4096, horizon=16, gamma=0.99.
// g[t,b] = sum_{h=0..15, t+h<T} g^h * r[t+h,b]*m[t+h,b]
//        + g^{min(t+16,T)-t} * V[min(t+15,T-1), b]
//
// R6 tile shape (64 cols x 64 output rows, 256 threads) with cp.async staging:
//  - phase 1: raw rew and msk rows [t0, t0+80) copied to smem via
//             cp.async.cg 16B (no dest regs, no load-use stall; OOB rows
//             zero-filled with src_bytes=0)
//  - phase 2: thread = (col, 16-row chunk); scalar backward sliding recurrence
//             S(t) = rm[t] + g*S(t+1) - g^16*rm[t+16], rm computed on the fly
//             from the two smem tiles.

#define TT 1024
#define BB 4096
#define HORIZON 16
#define BCOL 64                     // columns per block
#define TROWS 64                    // output rows per block
#define WROWS 80                    // staged rows (need 79; 80 = even split)

constexpr float GAMMA = 0.99f;

__host__ __device__ constexpr float gpow(int n) {
    float x = 1.0f;
    for (int i = 0; i < n; ++i) x *= GAMMA;
    return x;
}

__device__ __constant__ float GP[17] = {
    gpow(0),  gpow(1),  gpow(2),  gpow(3),  gpow(4),  gpow(5),
    gpow(6),  gpow(7),  gpow(8),  gpow(9),  gpow(10), gpow(11),
    gpow(12), gpow(13), gpow(14), gpow(15), gpow(16)
};

__device__ __forceinline__ void cp_async16(uint32_t dst_smem, const void* src,
                                           int src_bytes) {
    asm volatile("cp.async.cg.shared.global [%0], [%1], 16, %2;\n"
                 :: "r"(dst_smem), "l"(src), "r"(src_bytes));
}

__global__ __launch_bounds__(256)
void nstep_return_kernel(const float* __restrict__ rew,
                         const float* __restrict__ val,
                         const float* __restrict__ msk,
                         float* __restrict__ out)
{
    __shared__ float rewS[WROWS][BCOL];   // 20480 B
    __shared__ float mskS[WROWS][BCOL];   // 20480 B

    const int tid   = threadIdx.x;
    const int bcol0 = blockIdx.x * BCOL;    // first column of this block
    const int t0    = blockIdx.y * TROWS;   // first output row of this block

    constexpr float G16 = gpow(16);

    // ---- Phase 1: cp.async staging of rew/msk rows [t0, t0+WROWS) ----
    // 80 rows x 16 float4 = 1280 slots; 5 iterations x 2 arrays = 10 copies.
    uint32_t rewS_base, mskS_base;
    asm("{ .reg .u64 t; cvta.to.shared.u64 t, %1; cvt.u32.u64 %0, t; }"
        : "=r"(rewS_base) : "l"(&rewS[0][0]));
    asm("{ .reg .u64 t; cvta.to.shared.u64 t, %1; cvt.u32.u64 %0, t; }"
        : "=r"(mskS_base) : "l"(&mskS[0][0]));

#pragma unroll
    for (int it = 0; it < (WROWS * (BCOL / 4)) / 256; ++it) {
        const int i  = it * 256 + tid;
        const int r  = i >> 4;              // row in tile
        const int c4 = i & 15;              // float4 index in row
        const int tt = t0 + r;

        const int nbytes = (tt < TT) ? 16 : 0;          // zero-fill OOB rows
        const unsigned goff = (unsigned)(tt * BB + bcol0 + c4 * 4);
        const uint32_t soff = (uint32_t)((r * BCOL + c4 * 4) * 4);
        cp_async16(rewS_base + soff, rew + goff, nbytes);
        cp_async16(mskS_base + soff, msk + goff, nbytes);
    }
    asm volatile("cp.async.commit_group;\n");
    asm volatile("cp.async.wait_group 0;\n" ::: "memory");
    __syncthreads();

    // ---- Phase 2: scalar sliding-window recurrence ----
    const int col   = tid & (BCOL - 1);     // 0..63 (warp lanes = consecutive cols)
    const int chunk = tid >> 6;             // 0..3
    const int tl0   = chunk * 16;           // local row base
    const int b     = bcol0 + col;

    // S at local row tl0+15: Horner over rm rows [tl0+15 .. tl0+30].
    float S = 0.0f;
#pragma unroll
    for (int i = 30; i >= 15; --i) {
        S = fmaf(S, GAMMA, rewS[tl0 + i][col] * mskS[tl0 + i][col]);
    }

#pragma unroll
    for (int j = 15; j >= 0; --j) {
        const int t = t0 + tl0 + j;

        float boot;
        if (t + HORIZON <= TT) {
            boot = G16 * val[(unsigned)((t + HORIZON - 1) * BB + b)];
        } else {
            boot = GP[TT - t] * val[(unsigned)((TT - 1) * BB + b)];
        }
        out[(unsigned)(t * BB + b)] = S + boot;

        if (j > 0) {
            const float lo = rewS[tl0 + j - 1][col]  * mskS[tl0 + j - 1][col];
            const float hi = rewS[tl0 + j + 15][col] * mskS[tl0 + j + 15][col];
            S = fmaf(GAMMA, S, lo) - G16 * hi;
        }
    }
}

extern "C" void kernel_launch(void* const* d_in, const int* in_sizes, int n_in,
                              void* d_out, int out_size)
{
    const float* rewards = (const float*)d_in[0];
    const float* values  = (const float*)d_in[1];
    const float* masks   = (const float*)d_in[2];
    float*       out     = (float*)d_out;

    dim3 block(256);
    dim3 grid(BB / BCOL, TT / TROWS);   // (64, 16) = 1024 blocks
    nstep_return_kernel<<<grid, block>>>(rewards, values, masks, out);
}

// round 12
// speedup vs baseline: 1.5970x; 1.5104x over previous
#include <cuda_runtime.h>

// N-step discounted return, T=1024, B=4096, horizon=16, gamma=0.99.
// g[t,b] = sum_{h=0..15, t+h<T} g^h * r[t+h,b]*m[t+h,b]
//        + g^{min(t+16,T)-t} * V[min(t+15,T-1), b]
//
// R6 structure, taller tile: 64 cols x 128 output rows per 256-thread block.
//  - phase 1: cooperative float4 loads, rm = rew*mask -> 36.9KB smem
//             (144 rows; redundancy 1.125x)
//  - phase 2: thread = (col, 32-row chunk); scalar backward sliding recurrence
//             S(t) = rm[t] + g*S(t+1) - g^16*rm[t+16]
//  - grid = 512 CTAs at 6 CTAs/SM -> single wave (148*6 = 888 >= 512).

#define TT 1024
#define BB 4096
#define HORIZON 16
#define BCOL 64                     // columns per block
#define TROWS 128                   // output rows per block
#define WROWS 144                   // staged rows (need 143; 144 = even split)
#define CH 32                       // output rows per thread

constexpr float GAMMA = 0.99f;

__host__ __device__ constexpr float gpow(int n) {
    float x = 1.0f;
    for (int i = 0; i < n; ++i) x *= GAMMA;
    return x;
}

__device__ __constant__ float GP[17] = {
    gpow(0),  gpow(1),  gpow(2),  gpow(3),  gpow(4),  gpow(5),
    gpow(6),  gpow(7),  gpow(8),  gpow(9),  gpow(10), gpow(11),
    gpow(12), gpow(13), gpow(14), gpow(15), gpow(16)
};

__global__ __launch_bounds__(256)
void nstep_return_kernel(const float* __restrict__ rew,
                         const float* __restrict__ val,
                         const float* __restrict__ msk,
                         float* __restrict__ out)
{
    __shared__ float rm[WROWS][BCOL];   // 144*64*4 = 36864 B

    const int tid   = threadIdx.x;
    const int bcol0 = blockIdx.x * BCOL;    // first column of this block
    const int t0    = blockIdx.y * TROWS;   // first output row of this block

    constexpr float G16 = gpow(16);

    // ---- Phase 1: stage rm = rew*mask for rows [t0, t0+WROWS) ----
    // 144 rows x 16 float4 = 2304 slots = exactly 9 iterations of 256 threads.
#pragma unroll
    for (int it = 0; it < (WROWS * (BCOL / 4)) / 256; ++it) {
        const int i  = it * 256 + tid;
        const int r  = i >> 4;              // row in tile
        const int c4 = i & 15;              // float4 index in row
        const int tt = t0 + r;

        float4 p = make_float4(0.f, 0.f, 0.f, 0.f);
        if (tt < TT) {
            const unsigned off = (unsigned)(tt * BB + bcol0 + c4 * 4);
            const float4 rv = *reinterpret_cast<const float4*>(rew + off);
            const float4 mv = *reinterpret_cast<const float4*>(msk + off);
            p = make_float4(rv.x * mv.x, rv.y * mv.y, rv.z * mv.z, rv.w * mv.w);
        }
        *reinterpret_cast<float4*>(&rm[r][c4 * 4]) = p;
    }
    __syncthreads();

    // ---- Phase 2: scalar sliding-window recurrence ----
    const int col   = tid & (BCOL - 1);     // 0..63 (warp lanes = consecutive cols)
    const int chunk = tid >> 6;             // 0..3
    const int tl0   = chunk * CH;           // local row base
    const int b     = bcol0 + col;

    // S at local row tl0+CH-1: Horner over rm rows [tl0+CH-1 .. tl0+CH+14].
    float S = 0.0f;
#pragma unroll
    for (int i = CH + 14; i >= CH - 1; --i) {
        S = fmaf(S, GAMMA, rm[tl0 + i][col]);
    }

#pragma unroll
    for (int j = CH - 1; j >= 0; --j) {
        const int t = t0 + tl0 + j;

        float boot;
        if (t + HORIZON <= TT) {
            boot = G16 * val[(unsigned)((t + HORIZON - 1) * BB + b)];
        } else {
            boot = GP[TT - t] * val[(unsigned)((TT - 1) * BB + b)];
        }
        out[(unsigned)(t * BB + b)] = S + boot;

        if (j > 0) {
            // Slide window down: add rm[t-1], drop rm[t+15].
            S = fmaf(GAMMA, S, rm[tl0 + j - 1][col]) - G16 * rm[tl0 + j + 15][col];
        }
    }
}

extern "C" void kernel_launch(void* const* d_in, const int* in_sizes, int n_in,
                              void* d_out, int out_size)
{
    const float* rewards = (const float*)d_in[0];
    const float* values  = (const float*)d_in[1];
    const float* masks   = (const float*)d_in[2];
    float*       out     = (float*)d_out;

    dim3 block(256);
    dim3 grid(BB / BCOL, TT / TROWS);   // (64, 8) = 512 blocks, single wave
    nstep_return_kernel<<<grid, block>>>(rewards, values, masks, out);
}